// round 2
// baseline (speedup 1.0000x reference)
#include <cuda_runtime.h>
#include <math.h>

// Problem constants
#define Bq 8
#define Nn 1024
#define Tt 64
#define Cc 16
#define Ee 16384

// ---------------- scratch (device globals: no allocation allowed) ------------
__device__ int   g_deg[Nn];
__device__ float g_dinv[Nn];
__device__ int   g_off[Nn + 1];
__device__ int   g_cur[Nn];
__device__ int   g_adj[Ee];

// ---------------- packed f32x2 helpers (Blackwell FFMA2) --------------------
__device__ __forceinline__ unsigned long long pk2(float x) {
    unsigned int xi = __float_as_uint(x);
    unsigned long long r;
    asm("mov.b64 %0, {%1, %1};" : "=l"(r) : "r"(xi));
    return r;
}
__device__ __forceinline__ void fma2(unsigned long long& d, unsigned long long a,
                                     unsigned long long b) {
    asm("fma.rn.f32x2 %0, %1, %2, %3;" : "=l"(d) : "l"(a), "l"(b), "l"(d));
}

// ---------------- preprocessing kernels --------------------------------------
__global__ void k_zero() {
    int i = blockIdx.x * blockDim.x + threadIdx.x;
    if (i < Nn) g_deg[i] = 0;
}

__global__ void k_count(const int* __restrict__ ei) {
    int e = blockIdx.x * blockDim.x + threadIdx.x;
    if (e < Ee) atomicAdd(&g_deg[ei[Ee + e]], 1);
}

__global__ void k_scan() {
    __shared__ int s[Nn];
    int tid = threadIdx.x;
    int d0 = g_deg[tid];
    s[tid] = d0;
    g_dinv[tid] = rsqrtf((float)d0 + 1.0f);
    __syncthreads();
    for (int d = 1; d < Nn; d <<= 1) {
        int v = (tid >= d) ? s[tid - d] : 0;
        __syncthreads();
        s[tid] += v;
        __syncthreads();
    }
    int incl = s[tid];
    g_off[tid] = incl - d0;
    g_cur[tid] = incl - d0;
    if (tid == Nn - 1) g_off[Nn] = incl;
}

__global__ void k_fill(const int* __restrict__ ei) {
    int e = blockIdx.x * blockDim.x + threadIdx.x;
    if (e < Ee) {
        int c = ei[Ee + e];
        int pos = atomicAdd(&g_cur[c], 1);
        g_adj[pos] = ei[e];
    }
}

// Sort each node's incoming-row list ascending -> deterministic fp sum order.
__global__ void k_sort() {
    int n = blockIdx.x * blockDim.x + threadIdx.x;
    if (n < Nn) {
        int lo = g_off[n], hi = g_off[n + 1];
        for (int i = lo + 1; i < hi; i++) {
            int v = g_adj[i];
            int j = i - 1;
            while (j >= lo && g_adj[j] > v) { g_adj[j + 1] = g_adj[j]; j--; }
            g_adj[j + 1] = v;
        }
    }
}

// ---------------- main fused kernel ------------------------------------------
// grid = 1024 (one CTA per node n), 128 threads, loop b = 0..7 inside.
// smem layout (floats):
//   s_wc  [23*16*16] conv weights as [kk][c][o]         5888
//   s_wsT [64*65]    w_slin transposed [t][s] (pad 65)  4160
//   s_wg  [16*16]    w_gcn transposed [c][o]             256
//   s_btc [64]       concat conv biases                   64
//   s_bg  [16]       b_gcn                                16
//   s_bs  [64]       b_slin                               64
//   s_xe  [16][80]   x transposed + replication pad     1280
//   s_agg [16][64]   aggregated x (transposed)          1024
//   s_xl  [64][18]   gcn-transformed agg                1152
//   s_out [64][84]   output staging (80 used, pad 84)   5376
#define SM_WC 0
#define SM_WST (SM_WC + 5888)
#define SM_WG (SM_WST + 4160)
#define SM_BTC (SM_WG + 256)
#define SM_BG (SM_BTC + 64)
#define SM_BS (SM_BG + 16)
#define SM_XE (SM_BS + 64)
#define SM_AGG (SM_XE + 1280)
#define SM_XL (SM_AGG + 1024)
#define SM_OUT (SM_XL + 1152)
#define SM_TOTAL (SM_OUT + 5376)  // 19280 floats = 77120 bytes

__global__ void __launch_bounds__(128)
k_main(const float* __restrict__ x,
       const float* __restrict__ w_t2, const float* __restrict__ b_t2,
       const float* __restrict__ w_t3, const float* __restrict__ b_t3,
       const float* __restrict__ w_t6, const float* __restrict__ b_t6,
       const float* __restrict__ w_t12, const float* __restrict__ b_t12,
       const float* __restrict__ w_gcn, const float* __restrict__ b_gcn,
       const float* __restrict__ w_slin, const float* __restrict__ b_slin,
       float* __restrict__ out) {
    extern __shared__ float sm[];
    float* s_wc = sm + SM_WC;
    float* s_wsT = sm + SM_WST;
    float* s_wg = sm + SM_WG;
    float* s_btc = sm + SM_BTC;
    float* s_bg = sm + SM_BG;
    float* s_bs = sm + SM_BS;
    float* s_xe = sm + SM_XE;
    float* s_agg = sm + SM_AGG;
    float* s_xl = sm + SM_XL;
    float* s_out = sm + SM_OUT;

    const int n = blockIdx.x;
    const int tid = threadIdx.x;

    // ---- stage weights once per CTA ----
    for (int i = tid; i < 5888; i += 128) {
        int o = i & 15, c = (i >> 4) & 15, kk = i >> 8;
        float v;
        if (kk < 2)       v = w_t2[(o * 16 + c) * 2 + kk];
        else if (kk < 5)  v = w_t3[(o * 16 + c) * 3 + (kk - 2)];
        else if (kk < 11) v = w_t6[(o * 16 + c) * 6 + (kk - 5)];
        else              v = w_t12[(o * 16 + c) * 12 + (kk - 11)];
        s_wc[i] = v;
    }
    for (int i = tid; i < 4096; i += 128) {
        int s0 = i >> 6, t = i & 63;
        s_wsT[t * 65 + s0] = w_slin[i];
    }
    for (int i = tid; i < 256; i += 128) {
        int o = i >> 4, c = i & 15;
        s_wg[c * 16 + o] = w_gcn[i];
    }
    if (tid < 64) {
        s_btc[tid] = (tid < 16) ? b_t2[tid]
                   : (tid < 32) ? b_t3[tid - 16]
                   : (tid < 48) ? b_t6[tid - 32]
                                : b_t12[tid - 48];
        s_bs[tid] = b_slin[tid];
    }
    if (tid < 16) s_bg[tid] = b_gcn[tid];

    const int lo = g_off[n];
    const int hi = g_off[n + 1];
    const float dvn = g_dinv[n];
    __syncthreads();

    for (int b = 0; b < Bq; b++) {
        // ================= phase A: load self slab + gather neighbors ========
        const float* xb = x + (size_t)(b * Nn + n) * 1024;
        const float4* xb4 = (const float4*)xb;
        float4 a0 = __ldg(xb4 + tid * 2);
        float4 a1 = __ldg(xb4 + tid * 2 + 1);
        const int tt = tid >> 1;
        const int ch = (tid & 1) * 8;
        // s_xe transposed [c][6+t]
        s_xe[(ch + 0) * 80 + 6 + tt] = a0.x;
        s_xe[(ch + 1) * 80 + 6 + tt] = a0.y;
        s_xe[(ch + 2) * 80 + 6 + tt] = a0.z;
        s_xe[(ch + 3) * 80 + 6 + tt] = a0.w;
        s_xe[(ch + 4) * 80 + 6 + tt] = a1.x;
        s_xe[(ch + 5) * 80 + 6 + tt] = a1.y;
        s_xe[(ch + 6) * 80 + 6 + tt] = a1.z;
        s_xe[(ch + 7) * 80 + 6 + tt] = a1.w;

        const float sw = dvn * dvn;
        float acc[8];
        acc[0] = sw * a0.x; acc[1] = sw * a0.y; acc[2] = sw * a0.z; acc[3] = sw * a0.w;
        acc[4] = sw * a1.x; acc[5] = sw * a1.y; acc[6] = sw * a1.z; acc[7] = sw * a1.w;

        // 2-stage pipelined neighbor gather (CSR segment, sorted -> deterministic)
        int e = lo;
        float4 p0, p1;
        float pw = 0.0f;
        if (e < hi) {
            int r = __ldg(&g_adj[e]);
            pw = __ldg(&g_dinv[r]) * dvn;
            const float4* src = (const float4*)(x + (size_t)(b * Nn + r) * 1024) + tid * 2;
            p0 = __ldg(src); p1 = __ldg(src + 1);
        }
        while (e < hi) {
            float4 c0 = p0, c1 = p1;
            float cw = pw;
            ++e;
            if (e < hi) {
                int r = __ldg(&g_adj[e]);
                pw = __ldg(&g_dinv[r]) * dvn;
                const float4* src = (const float4*)(x + (size_t)(b * Nn + r) * 1024) + tid * 2;
                p0 = __ldg(src); p1 = __ldg(src + 1);
            }
            acc[0] += cw * c0.x; acc[1] += cw * c0.y; acc[2] += cw * c0.z; acc[3] += cw * c0.w;
            acc[4] += cw * c1.x; acc[5] += cw * c1.y; acc[6] += cw * c1.z; acc[7] += cw * c1.w;
        }
        #pragma unroll
        for (int i = 0; i < 8; i++) s_agg[(ch + i) * 64 + tt] = acc[i];

        // replication-pad edges of s_xe (values straight from gmem, no dep on smem)
        if (tid < 16) {
            float ev0 = __ldg(xb + tid);
            float ev1 = __ldg(xb + 1008 + tid);
            float* rowp = &s_xe[tid * 80];
            #pragma unroll
            for (int j = 0; j < 6; j++) rowp[j] = ev0;
            #pragma unroll
            for (int j = 70; j < 80; j++) rowp[j] = ev1;
        }
        __syncthreads();

        // ================= phase B: GCN transform (agg_x @ Wg^T + bg) ========
        {
            int t = tid & 63, h = tid >> 6;
            unsigned long long tacc[4];
            #pragma unroll
            for (int j = 0; j < 4; j++)
                tacc[j] = *(const unsigned long long*)&s_bg[h * 8 + 2 * j];
            #pragma unroll
            for (int c = 0; c < 16; c++) {
                unsigned long long a2 = pk2(s_agg[c * 64 + t]);
                #pragma unroll
                for (int j = 0; j < 4; j++) {
                    unsigned long long w2 =
                        *(const unsigned long long*)&s_wg[c * 16 + h * 8 + 2 * j];
                    fma2(tacc[j], a2, w2);
                }
            }
            #pragma unroll
            for (int j = 0; j < 4; j++)
                *(unsigned long long*)&s_xl[t * 18 + h * 8 + 2 * j] = tacc[j];
        }

        // ================= phase C: 4-branch temporal conv ====================
        {
            const int tg = tid & 15, og = tid >> 4;  // og slow -> weight broadcast
            const int t0 = tg << 2;
            unsigned long long acc2[16];
            #pragma unroll
            for (int i = 0; i < 16; i++) acc2[i] = 0ULL;
            #pragma unroll
            for (int c = 0; c < 16; c++) {
                const float4* xr4 = (const float4*)&s_xe[c * 80 + t0];
                float4 x0 = xr4[0], x1 = xr4[1], x2 = xr4[2], x3 = xr4[3];
                unsigned long long xp[16];
                xp[0] = pk2(x0.x); xp[1] = pk2(x0.y); xp[2] = pk2(x0.z); xp[3] = pk2(x0.w);
                xp[4] = pk2(x1.x); xp[5] = pk2(x1.y); xp[6] = pk2(x1.z); xp[7] = pk2(x1.w);
                xp[8] = pk2(x2.x); xp[9] = pk2(x2.y); xp[10] = pk2(x2.z); xp[11] = pk2(x2.w);
                xp[12] = pk2(x3.x); xp[13] = pk2(x3.y); xp[14] = pk2(x3.z); xp[15] = pk2(x3.w);
                const float* wbase = &s_wc[c * 16 + (og << 1)];
                #pragma unroll
                for (int kk = 0; kk < 23; kk++) {
                    const int br = (kk < 2) ? 0 : ((kk < 5) ? 1 : ((kk < 11) ? 2 : 3));
                    const int sft = (kk < 2) ? (kk + 6)
                                  : ((kk < 5) ? (kk + 3)
                                  : ((kk < 11) ? (kk - 1) : (kk - 11)));
                    unsigned long long w2 =
                        *(const unsigned long long*)(wbase + kk * 256);
                    fma2(acc2[br * 4 + 0], xp[sft + 0], w2);
                    fma2(acc2[br * 4 + 1], xp[sft + 1], w2);
                    fma2(acc2[br * 4 + 2], xp[sft + 2], w2);
                    fma2(acc2[br * 4 + 3], xp[sft + 3], w2);
                }
            }
            #pragma unroll
            for (int br = 0; br < 4; br++)
                #pragma unroll
                for (int dt = 0; dt < 4; dt++)
                    *(unsigned long long*)
                        &s_out[(t0 + dt) * 84 + br * 16 + (og << 1)] = acc2[br * 4 + dt];
        }
        __syncthreads();

        // ================= phase D: slin (xl @ Wslin^T + bs) ==================
        {
            int ss = tid & 63, h = tid >> 6;
            unsigned long long b2 = pk2(s_bs[ss]);
            unsigned long long sacc[4];
            #pragma unroll
            for (int j = 0; j < 4; j++) sacc[j] = b2;
            #pragma unroll 4
            for (int t = 0; t < 64; t++) {
                unsigned long long w2 = pk2(s_wsT[t * 65 + ss]);
                #pragma unroll
                for (int j = 0; j < 4; j++) {
                    unsigned long long xl2 =
                        *(const unsigned long long*)&s_xl[t * 18 + h * 8 + 2 * j];
                    fma2(sacc[j], xl2, w2);
                }
            }
            #pragma unroll
            for (int j = 0; j < 4; j++)
                *(unsigned long long*)&s_out[ss * 84 + 64 + h * 8 + 2 * j] = sacc[j];
        }
        __syncthreads();

        // ================= phase E: bias + tanh + coalesced store =============
        {
            float* op = out + (size_t)(b * Nn + n) * 5120;
            #pragma unroll
            for (int it = 0; it < 10; it++) {
                int i = it * 512 + tid * 4;
                int row = i / 80;
                int col = i - row * 80;
                float4 v = *(const float4*)&s_out[row * 84 + col];
                if (col < 64) {
                    v.x += s_btc[col]; v.y += s_btc[col + 1];
                    v.z += s_btc[col + 2]; v.w += s_btc[col + 3];
                } else {
                    float bb = s_bs[row];
                    v.x += bb; v.y += bb; v.z += bb; v.w += bb;
                }
                v.x = tanhf(v.x); v.y = tanhf(v.y);
                v.z = tanhf(v.z); v.w = tanhf(v.w);
                *(float4*)&op[row * 80 + col] = v;
            }
        }
        __syncthreads();
    }
}

// ---------------- launch ------------------------------------------------------
extern "C" void kernel_launch(void* const* d_in, const int* in_sizes, int n_in,
                              void* d_out, int out_size) {
    const float* x = (const float*)d_in[0];
    const int* ei = (const int*)d_in[1];
    const float* w_t2 = (const float*)d_in[2];
    const float* b_t2 = (const float*)d_in[3];
    const float* w_t3 = (const float*)d_in[4];
    const float* b_t3 = (const float*)d_in[5];
    const float* w_t6 = (const float*)d_in[6];
    const float* b_t6 = (const float*)d_in[7];
    const float* w_t12 = (const float*)d_in[8];
    const float* b_t12 = (const float*)d_in[9];
    const float* w_gcn = (const float*)d_in[10];
    const float* b_gcn = (const float*)d_in[11];
    const float* w_slin = (const float*)d_in[12];
    const float* b_slin = (const float*)d_in[13];
    float* out = (float*)d_out;

    k_zero<<<4, 256>>>();
    k_count<<<64, 256>>>(ei);
    k_scan<<<1, 1024>>>();
    k_fill<<<64, 256>>>(ei);
    k_sort<<<4, 256>>>();

    cudaFuncSetAttribute(k_main, cudaFuncAttributeMaxDynamicSharedMemorySize,
                         SM_TOTAL * (int)sizeof(float));
    k_main<<<Nn, 128, SM_TOTAL * sizeof(float)>>>(
        x, w_t2, b_t2, w_t3, b_t3, w_t6, b_t6, w_t12, b_t12,
        w_gcn, b_gcn, w_slin, b_slin, out);
}

// round 3
// speedup vs baseline: 1.2137x; 1.2137x over previous
#include <cuda_runtime.h>
#include <math.h>

// Problem constants
#define Bq 8
#define Nn 1024
#define Tt 64
#define Cc 16
#define Ee 16384

// ---------------- scratch (device globals: no allocation allowed) ------------
__device__ float g_dinv[Nn];
__device__ int   g_off[Nn + 1];
__device__ int   g_adj[Ee];

// ---------------- packed f32x2 helpers (Blackwell FFMA2) --------------------
__device__ __forceinline__ unsigned long long pk2(float x) {
    unsigned int xi = __float_as_uint(x);
    unsigned long long r;
    asm("mov.b64 %0, {%1, %1};" : "=l"(r) : "r"(xi));
    return r;
}
__device__ __forceinline__ void fma2(unsigned long long& d, unsigned long long a,
                                     unsigned long long b) {
    asm("fma.rn.f32x2 %0, %1, %2, %3;" : "=l"(d) : "l"(a), "l"(b), "l"(d));
}

// ---------------- single-CTA CSR build ---------------------------------------
// 1 CTA, 1024 threads: zero -> count(smem atomics) -> scan -> fill -> sort.
__global__ void k_prep(const int* __restrict__ ei) {
    __shared__ int sdeg[Nn];
    __shared__ int scur[Nn];
    const int tid = threadIdx.x;
    sdeg[tid] = 0;
    __syncthreads();
    for (int e = tid; e < Ee; e += 1024) atomicAdd(&sdeg[ei[Ee + e]], 1);
    __syncthreads();
    const int d0 = sdeg[tid];
    g_dinv[tid] = rsqrtf((float)d0 + 1.0f);
    scur[tid] = d0;
    __syncthreads();
    for (int d = 1; d < Nn; d <<= 1) {
        int v = (tid >= d) ? scur[tid - d] : 0;
        __syncthreads();
        scur[tid] += v;
        __syncthreads();
    }
    const int incl = scur[tid];
    const int off = incl - d0;
    g_off[tid] = off;
    if (tid == Nn - 1) g_off[Nn] = incl;
    __syncthreads();
    scur[tid] = off;
    __syncthreads();
    for (int e = tid; e < Ee; e += 1024) {
        int c = ei[Ee + e];
        int pos = atomicAdd(&scur[c], 1);
        g_adj[pos] = ei[e];
    }
    __syncthreads();
    // per-node insertion sort -> deterministic fp sum order
    {
        int lo = off, hi = off + d0;
        for (int i = lo + 1; i < hi; i++) {
            int v = g_adj[i];
            int j = i - 1;
            while (j >= lo && g_adj[j] > v) { g_adj[j + 1] = g_adj[j]; j--; }
            g_adj[j + 1] = v;
        }
    }
}

// ---------------- unified work kernel ----------------------------------------
// grid = 3072, 128 threads. bid%3: {0,1} -> conv role, {2} -> spatial role.
//   conv role:    q = (bid/3)*2 + bid%3 in [0,2048); n=q>>1, b in [(q&1)*4, +4)
//   spatial role: n = bid/3 in [0,1024); b in [0,8)
//
// smem union (floats, 11584 total = 46336 B, static):
//   conv:    s_wc[5888] | s_btc[64] | s_xe[16*80=1280] | s_out[64*68=4352]
//   spatial: s_wg[256] | s_bg[16] | s_bs[64] (pad to 336) | s_wsT[64*65=4160]
//            | s_agg[16*64=1024] | s_xl[64*18=1152]
#define SMEM_FLOATS 11584

__global__ void __launch_bounds__(128, 4)
k_work(const float* __restrict__ x,
       const float* __restrict__ w_t2, const float* __restrict__ b_t2,
       const float* __restrict__ w_t3, const float* __restrict__ b_t3,
       const float* __restrict__ w_t6, const float* __restrict__ b_t6,
       const float* __restrict__ w_t12, const float* __restrict__ b_t12,
       const float* __restrict__ w_gcn, const float* __restrict__ b_gcn,
       const float* __restrict__ w_slin, const float* __restrict__ b_slin,
       float* __restrict__ out) {
    __shared__ __align__(16) float sm[SMEM_FLOATS];
    const int bid = blockIdx.x;
    const int tid = threadIdx.x;
    const int cid = bid / 3;
    const int role = bid - cid * 3;

    if (role < 2) {
        // ==================== CONV ROLE =====================================
        float* s_wc = sm;             // [kk][c][o] 23*16*16
        float* s_btc = sm + 5888;     // concat conv biases [64]
        float* s_xe = sm + 5952;      // [16][80] transposed + repl pad
        float* s_out = sm + 7232;     // [64][68]

        const int q = cid * 2 + role;
        const int n = q >> 1;
        const int bh = (q & 1) * 4;

        for (int i = tid; i < 5888; i += 128) {
            int o = i & 15, c = (i >> 4) & 15, kk = i >> 8;
            float v;
            if (kk < 2)       v = w_t2[(o * 16 + c) * 2 + kk];
            else if (kk < 5)  v = w_t3[(o * 16 + c) * 3 + (kk - 2)];
            else if (kk < 11) v = w_t6[(o * 16 + c) * 6 + (kk - 5)];
            else              v = w_t12[(o * 16 + c) * 12 + (kk - 11)];
            s_wc[i] = v;
        }
        if (tid < 64) {
            s_btc[tid] = (tid < 16) ? b_t2[tid]
                       : (tid < 32) ? b_t3[tid - 16]
                       : (tid < 48) ? b_t6[tid - 32]
                                    : b_t12[tid - 48];
        }
        __syncthreads();

        for (int b = bh; b < bh + 4; b++) {
            const float* xb = x + (size_t)(b * Nn + n) * 1024;
            const float4* xb4 = (const float4*)xb;
            float4 a0 = __ldg(xb4 + tid * 2);
            float4 a1 = __ldg(xb4 + tid * 2 + 1);
            const int tt = tid >> 1;
            const int ch = (tid & 1) * 8;
            s_xe[(ch + 0) * 80 + 6 + tt] = a0.x;
            s_xe[(ch + 1) * 80 + 6 + tt] = a0.y;
            s_xe[(ch + 2) * 80 + 6 + tt] = a0.z;
            s_xe[(ch + 3) * 80 + 6 + tt] = a0.w;
            s_xe[(ch + 4) * 80 + 6 + tt] = a1.x;
            s_xe[(ch + 5) * 80 + 6 + tt] = a1.y;
            s_xe[(ch + 6) * 80 + 6 + tt] = a1.z;
            s_xe[(ch + 7) * 80 + 6 + tt] = a1.w;
            if (tid < 16) {
                float ev0 = __ldg(xb + tid);
                float ev1 = __ldg(xb + 1008 + tid);
                float* rowp = &s_xe[tid * 80];
                #pragma unroll
                for (int j = 0; j < 6; j++) rowp[j] = ev0;
                #pragma unroll
                for (int j = 70; j < 80; j++) rowp[j] = ev1;
            }
            __syncthreads();

            {
                const int tg = tid & 15, og = tid >> 4;  // og slow: weight bcast
                const int t0 = tg << 2;
                unsigned long long acc2[16];
                #pragma unroll
                for (int br = 0; br < 4; br++)
                    #pragma unroll
                    for (int dt = 0; dt < 4; dt++)
                        acc2[br * 4 + dt] =
                            *(const unsigned long long*)&s_btc[br * 16 + (og << 1)];
                #pragma unroll
                for (int c = 0; c < 16; c++) {
                    const float4* xr4 = (const float4*)&s_xe[c * 80 + t0];
                    float4 x0 = xr4[0], x1 = xr4[1], x2 = xr4[2], x3 = xr4[3];
                    unsigned long long xp[16];
                    xp[0] = pk2(x0.x); xp[1] = pk2(x0.y); xp[2] = pk2(x0.z); xp[3] = pk2(x0.w);
                    xp[4] = pk2(x1.x); xp[5] = pk2(x1.y); xp[6] = pk2(x1.z); xp[7] = pk2(x1.w);
                    xp[8] = pk2(x2.x); xp[9] = pk2(x2.y); xp[10] = pk2(x2.z); xp[11] = pk2(x2.w);
                    xp[12] = pk2(x3.x); xp[13] = pk2(x3.y); xp[14] = pk2(x3.z); xp[15] = pk2(x3.w);
                    const float* wbase = &s_wc[c * 16 + (og << 1)];
                    #pragma unroll
                    for (int kk = 0; kk < 23; kk++) {
                        const int br = (kk < 2) ? 0 : ((kk < 5) ? 1 : ((kk < 11) ? 2 : 3));
                        const int sft = (kk < 2) ? (kk + 6)
                                      : ((kk < 5) ? (kk + 3)
                                      : ((kk < 11) ? (kk - 1) : (kk - 11)));
                        unsigned long long w2 =
                            *(const unsigned long long*)(wbase + kk * 256);
                        fma2(acc2[br * 4 + 0], xp[sft + 0], w2);
                        fma2(acc2[br * 4 + 1], xp[sft + 1], w2);
                        fma2(acc2[br * 4 + 2], xp[sft + 2], w2);
                        fma2(acc2[br * 4 + 3], xp[sft + 3], w2);
                    }
                }
                #pragma unroll
                for (int br = 0; br < 4; br++)
                    #pragma unroll
                    for (int dt = 0; dt < 4; dt++)
                        *(unsigned long long*)
                            &s_out[(t0 + dt) * 68 + br * 16 + (og << 1)] = acc2[br * 4 + dt];
            }
            __syncthreads();

            {
                float* op = out + ((size_t)(b * Nn + n) * 64) * 80;
                #pragma unroll
                for (int it = 0; it < 8; it++) {
                    int i = it * 512 + tid * 4;
                    int row = i >> 6;
                    int col = i & 63;
                    float4 v = *(const float4*)&s_out[row * 68 + col];
                    v.x = tanhf(v.x); v.y = tanhf(v.y);
                    v.z = tanhf(v.z); v.w = tanhf(v.w);
                    *(float4*)&op[row * 80 + col] = v;
                }
            }
            __syncthreads();
        }
    } else {
        // ==================== SPATIAL ROLE ==================================
        float* s_wg = sm;            // [c][o] 16*16
        float* s_bg = sm + 256;      // [16]
        float* s_bs = sm + 272;      // [64]
        float* s_wsT = sm + 336;     // [t][s] stride 65
        float* s_agg = sm + 4496;    // [16][64]
        float* s_xl = sm + 5520;     // [64][18]

        const int n = cid;

        for (int i = tid; i < 4096; i += 128) {
            int s0 = i >> 6, t = i & 63;
            s_wsT[t * 65 + s0] = w_slin[i];
        }
        for (int i = tid; i < 256; i += 128) {
            int o = i >> 4, c = i & 15;
            s_wg[c * 16 + o] = w_gcn[i];
        }
        if (tid < 64) s_bs[tid] = b_slin[tid];
        if (tid < 16) s_bg[tid] = b_gcn[tid];

        const int lo = g_off[n];
        const int cnt = g_off[n + 1] - lo;
        const float dvn = g_dinv[n];
        __syncthreads();

        for (int b = 0; b < Bq; b++) {
            // ---- gather: self + neighbors, 4-wide bursts ----
            const float* xb = x + (size_t)(b * Nn + n) * 1024;
            const float4* xb4 = (const float4*)xb;
            float4 a0 = __ldg(xb4 + tid * 2);
            float4 a1 = __ldg(xb4 + tid * 2 + 1);
            const int tt = tid >> 1;
            const int ch = (tid & 1) * 8;

            const float sw = dvn * dvn;
            float acc[8];
            acc[0] = sw * a0.x; acc[1] = sw * a0.y; acc[2] = sw * a0.z; acc[3] = sw * a0.w;
            acc[4] = sw * a1.x; acc[5] = sw * a1.y; acc[6] = sw * a1.z; acc[7] = sw * a1.w;

            for (int k = 0; k < cnt; k += 4) {
                float4 p0[4], p1[4];
                float w[4];
                #pragma unroll
                for (int j = 0; j < 4; j++) {
                    if (k + j < cnt) {
                        int r = __ldg(&g_adj[lo + k + j]);
                        w[j] = __ldg(&g_dinv[r]) * dvn;
                        const float4* src =
                            (const float4*)(x + (size_t)(b * Nn + r) * 1024) + tid * 2;
                        p0[j] = __ldg(src);
                        p1[j] = __ldg(src + 1);
                    }
                }
                #pragma unroll
                for (int j = 0; j < 4; j++) {
                    if (k + j < cnt) {
                        acc[0] += w[j] * p0[j].x; acc[1] += w[j] * p0[j].y;
                        acc[2] += w[j] * p0[j].z; acc[3] += w[j] * p0[j].w;
                        acc[4] += w[j] * p1[j].x; acc[5] += w[j] * p1[j].y;
                        acc[6] += w[j] * p1[j].z; acc[7] += w[j] * p1[j].w;
                    }
                }
            }
            #pragma unroll
            for (int i = 0; i < 8; i++) s_agg[(ch + i) * 64 + tt] = acc[i];
            __syncthreads();

            // ---- GCN transform: xl[t][o] = agg[c][t] @ wg[c][o] + bg ----
            {
                int t = tid & 63, h = tid >> 6;
                unsigned long long tacc[4];
                #pragma unroll
                for (int j = 0; j < 4; j++)
                    tacc[j] = *(const unsigned long long*)&s_bg[h * 8 + 2 * j];
                #pragma unroll
                for (int c = 0; c < 16; c++) {
                    unsigned long long a2 = pk2(s_agg[c * 64 + t]);
                    #pragma unroll
                    for (int j = 0; j < 4; j++) {
                        unsigned long long w2 =
                            *(const unsigned long long*)&s_wg[c * 16 + h * 8 + 2 * j];
                        fma2(tacc[j], a2, w2);
                    }
                }
                #pragma unroll
                for (int j = 0; j < 4; j++)
                    *(unsigned long long*)&s_xl[t * 18 + h * 8 + 2 * j] = tacc[j];
            }
            __syncthreads();

            // ---- slin + tanh + direct store (cols 64..79) ----
            {
                int ss = tid & 63, h = tid >> 6;
                unsigned long long b2 = pk2(s_bs[ss]);
                unsigned long long sacc[4];
                #pragma unroll
                for (int j = 0; j < 4; j++) sacc[j] = b2;
                #pragma unroll 4
                for (int t = 0; t < 64; t++) {
                    unsigned long long w2 = pk2(s_wsT[t * 65 + ss]);
                    #pragma unroll
                    for (int j = 0; j < 4; j++) {
                        unsigned long long xl2 =
                            *(const unsigned long long*)&s_xl[t * 18 + h * 8 + 2 * j];
                        fma2(sacc[j], xl2, w2);
                    }
                }
                float v[8];
                #pragma unroll
                for (int j = 0; j < 4; j++) {
                    unsigned int lo32, hi32;
                    asm("mov.b64 {%0, %1}, %2;" : "=r"(lo32), "=r"(hi32) : "l"(sacc[j]));
                    v[2 * j] = tanhf(__uint_as_float(lo32));
                    v[2 * j + 1] = tanhf(__uint_as_float(hi32));
                }
                float* op = out + ((size_t)(b * Nn + n) * 64 + ss) * 80 + 64 + h * 8;
                float4 v0 = {v[0], v[1], v[2], v[3]};
                float4 v1 = {v[4], v[5], v[6], v[7]};
                *(float4*)op = v0;
                *(float4*)(op + 4) = v1;
            }
            __syncthreads();
        }
    }
}

// ---------------- launch ------------------------------------------------------
extern "C" void kernel_launch(void* const* d_in, const int* in_sizes, int n_in,
                              void* d_out, int out_size) {
    const float* x = (const float*)d_in[0];
    const int* ei = (const int*)d_in[1];
    const float* w_t2 = (const float*)d_in[2];
    const float* b_t2 = (const float*)d_in[3];
    const float* w_t3 = (const float*)d_in[4];
    const float* b_t3 = (const float*)d_in[5];
    const float* w_t6 = (const float*)d_in[6];
    const float* b_t6 = (const float*)d_in[7];
    const float* w_t12 = (const float*)d_in[8];
    const float* b_t12 = (const float*)d_in[9];
    const float* w_gcn = (const float*)d_in[10];
    const float* b_gcn = (const float*)d_in[11];
    const float* w_slin = (const float*)d_in[12];
    const float* b_slin = (const float*)d_in[13];
    float* out = (float*)d_out;

    k_prep<<<1, 1024>>>(ei);
    k_work<<<3072, 128>>>(x, w_t2, b_t2, w_t3, b_t3, w_t6, b_t6, w_t12, b_t12,
                          w_gcn, b_gcn, w_slin, b_slin, out);
}